// round 7
// baseline (speedup 1.0000x reference)
#include <cuda_runtime.h>

#define HH 360
#define WW 720
#define W2 360
#define BB 8
#define TYS 10
#define NITER (TYS + 6)       // 16
#define NTAB  (NITER + 2)     // 18 rows: y0-5 .. y0+TYS+2
#define SEGS 13               // 13*28 = 364 >= 360 float2 cols (wrap, dup writes identical)
#define BANDS (HH / TYS)      // 36
#define NSTEPS 20
#define FULLM 0xffffffffu

// Ping-pong scratch (allocation-free: __device__ globals).
__device__ float g_bufA[BB * HH * WW];
__device__ float g_bufB[BB * HH * WW];

__device__ __forceinline__ float2 f2z() { return make_float2(0.f, 0.f); }
__device__ __forceinline__ int rclamp(int r) { return min(max(r, 0), HH - 1); }

// Two fused timesteps, 6-stage rolling pipeline down y.
// IN=true: interior band — no clamps, no validity checks, central dT/dy only.
template <bool IN>
__device__ __forceinline__ void run_band(
    const float2* __restrict__ Tb, const float2* __restrict__ ub,
    const float2* __restrict__ vb, const float2* __restrict__ mb,
    float2* __restrict__ Ob, const float* __restrict__ sI,
    const int y0, const int c, const bool emitl, const bool zL, const bool zR,
    const float sdy, const float s2dy)
{
    const float DTC = 600.0f;

    float2 T0, T1, TPf, uPf, vPf, mPf;
    {
        const int r0 = IN ? (y0 - 4) : rclamp(y0 - 4);
        const int r1 = IN ? (y0 - 3) : rclamp(y0 - 3);
        const int r2 = IN ? (y0 - 2) : rclamp(y0 - 2);
        T0  = Tb[r0 * W2 + c];
        T1  = Tb[r1 * W2 + c];
        TPf = Tb[r2 * W2 + c];
        uPf = ub[r1 * W2 + c];
        vPf = vb[r1 * W2 + c];
        mPf = mb[r1 * W2 + c];
    }

    float2 h1a = f2z(), h1b = f2z(), h1c = f2z();
    float2 F1a = f2z(), F1b = f2z(), F1c = f2z();
    float2 h2a = f2z(), h2b = f2z(), h2c = f2z();
    float2 uC = f2z(), u1 = f2z(), u2 = f2z();
    float2 vC = f2z(), v1 = f2z(), v2 = f2z();
    float2 mC = f2z(), m1 = f2z(), m2 = f2z(), m3 = f2z();

#pragma unroll
    for (int k = 0; k < NITER; ++k) {
        const int a = y0 - 3 + k;       // step-1 advection row

        // ring shifts (renamed by full unroll)
        m3 = m2; m2 = m1; m1 = mC;
        u2 = u1; u1 = uC;
        v2 = v1; v1 = vC;
        const float2 T2 = TPf;
        uC = uPf; vC = vPf; mC = mPf;

        // prefetch next iteration's rows (T: a+2, u/v/m: a+1)
        {
            const int rT = IN ? (a + 2) : rclamp(a + 2);
            const int rU = IN ? (a + 1) : rclamp(a + 1);
            TPf = Tb[rT * W2 + c];
            uPf = ub[rU * W2 + c];
            vPf = vb[rU * W2 + c];
            mPf = mb[rU * W2 + c];
        }

        // ---- stage 1: advection step 1 + horizontal (1,2,1) at row a
        h1a = h1b; h1b = h1c;
        {
            const float iA = sI[k + 2];
            float dty0, dty1;
            if (IN) {
                dty0 = (T2.x - T0.x) * s2dy;
                dty1 = (T2.y - T0.y) * s2dy;
            } else {
                const float cA = (a == 0) ? sdy  : ((a == HH - 1) ? 0.f  : s2dy);
                const float cB = (a == 0) ? -sdy : ((a == HH - 1) ? sdy  : 0.f);
                const float cC = (a == 0) ? 0.f  : ((a == HH - 1) ? -sdy : -s2dy);
                dty0 = cA * T2.x + cB * T1.x + cC * T0.x;
                dty1 = cA * T2.y + cB * T1.y + cC * T0.y;
            }
            const float lf = __shfl_up_sync(FULLM, T1.y, 1);
            const float rt = __shfl_down_sync(FULLM, T1.x, 1);
            const float A0 = T1.x - DTC * (uC.x * ((T1.y - lf) * iA) + vC.x * dty0) * mC.x;
            const float A1 = T1.y - DTC * (uC.y * ((rt - T1.x) * iA) + vC.y * dty1) * mC.y;
            float Am = __shfl_up_sync(FULLM, A1, 1);
            float Ap = __shfl_down_sync(FULLM, A0, 1);
            Am = zL ? 0.f : Am;
            Ap = zR ? 0.f : Ap;
            float hx = Am + 2.f * A0 + A1;
            float hy = A0 + 2.f * A1 + Ap;
            if (!IN && !(a >= 0 && a < HH)) { hx = 0.f; hy = 0.f; }
            h1c.x = hx; h1c.y = hy;
        }

        // ---- stage 2: vertical (1,2,1)/16 * mask -> F1 at row f = a-1
        F1a = F1b; F1b = F1c;
        {
            float fx = (h1a.x + 2.f * h1b.x + h1c.x) * 0.0625f * m1.x;
            float fy = (h1a.y + 2.f * h1b.y + h1c.y) * 0.0625f * m1.y;
            if (!IN) { const int f = a - 1; if (!(f >= 0 && f < HH)) { fx = 0.f; fy = 0.f; } }
            F1c.x = fx; F1c.y = fy;
        }

        // ---- stage 3: advection step 2 + horizontal (1,2,1) at row g = a-2
        h2a = h2b; h2b = h2c;
        {
            const int g = a - 2;
            const float iG = sI[k];
            float dty0, dty1;
            if (IN) {
                dty0 = (F1c.x - F1a.x) * s2dy;
                dty1 = (F1c.y - F1a.y) * s2dy;
            } else {
                const float cA = (g == 0) ? sdy  : ((g == HH - 1) ? 0.f  : s2dy);
                const float cB = (g == 0) ? -sdy : ((g == HH - 1) ? sdy  : 0.f);
                const float cC = (g == 0) ? 0.f  : ((g == HH - 1) ? -sdy : -s2dy);
                dty0 = cA * F1c.x + cB * F1b.x + cC * F1a.x;
                dty1 = cA * F1c.y + cB * F1b.y + cC * F1a.y;
            }
            const float lf = __shfl_up_sync(FULLM, F1b.y, 1);
            const float rt = __shfl_down_sync(FULLM, F1b.x, 1);
            const float A0 = F1b.x - DTC * (u2.x * ((F1b.y - lf) * iG) + v2.x * dty0) * m2.x;
            const float A1 = F1b.y - DTC * (u2.y * ((rt - F1b.x) * iG) + v2.y * dty1) * m2.y;
            float Am = __shfl_up_sync(FULLM, A1, 1);
            float Ap = __shfl_down_sync(FULLM, A0, 1);
            Am = zL ? 0.f : Am;
            Ap = zR ? 0.f : Ap;
            float hx = Am + 2.f * A0 + A1;
            float hy = A0 + 2.f * A1 + Ap;
            if (!IN && !(g >= 0 && g < HH)) { hx = 0.f; hy = 0.f; }
            h2c.x = hx; h2c.y = hy;
        }

        // ---- stage 4: vertical (1,2,1)/16 * mask -> emit row e = a-3
        if (k >= 6) {                       // compile-time prune of fill iters
            if (emitl) {
                const int e = a - 3;        // in [y0, y0+TYS)
                float2 o;
                o.x = (h2a.x + 2.f * h2b.x + h2c.x) * 0.0625f * m3.x;
                o.y = (h2a.y + 2.f * h2b.y + h2c.y) * 0.0625f * m3.y;
                Ob[e * W2 + c] = o;
            }
        }

        T0 = T1; T1 = T2;
    }
}

__global__ __launch_bounds__(128, 6) void ocean_step2(
    const float* __restrict__ Tin, float* __restrict__ Tout,
    const float* __restrict__ ug, const float* __restrict__ vg,
    const float* __restrict__ lat, const float* __restrict__ lon,
    const float* __restrict__ mask)
{
    __shared__ float sIw[4][NTAB];    // per-warp 1/(2dx) tables

    const int tid  = threadIdx.x;
    const int lane = tid & 31;
    const int wib  = tid >> 5;
    const int ws   = blockIdx.x * 4 + wib;
    const int seg  = ws % SEGS;
    const int rem  = ws / SEGS;
    const int band = rem % BANDS;
    const int b    = rem / BANDS;
    const int y0   = band * TYS;

    // lane -> float2 column (wrapped). Lanes 2..29 emit.
    int c = seg * 28 - 2 + lane;
    c += (c < 0) ? W2 : 0;
    c -= (c >= W2) ? W2 : 0;
    const bool emitl = (lane >= 2) && (lane <= 29);
    const bool zL = (c == 0);
    const bool zR = (c == W2 - 1);

    const float DEG2RAD = 0.017453292519943295f;
    const float RE = 6371000.0f;
    const float dlat = lat[1] - lat[0];
    const float dlon = lon[1] - lon[0];
    const float dy   = RE * DEG2RAD * fabsf(dlat);
    const float sgn  = (dlat > 0.f) ? 1.f : -1.f;
    const float sdy  = sgn / dy;
    const float s2dy = sgn / (2.f * dy);
    const float xden = 2.f * RE * DEG2RAD * dlon;

    // fill this warp's inv2dx table: rows y0-5 .. y0+TYS+2 (clamped)
    if (lane < NTAB) {
        const int r = rclamp(y0 - 5 + lane);
        sIw[wib][lane] = __fdividef(1.f, xden * __cosf(lat[r] * DEG2RAD));
    }
    __syncwarp();

    const float2* Tb = (const float2*)(Tin + (size_t)b * HH * WW);
    const float2* ub = (const float2*)(ug  + (size_t)b * HH * WW);
    const float2* vb = (const float2*)(vg  + (size_t)b * HH * WW);
    const float2* mb = (const float2*)mask;
    float2*       Ob = (float2*)(Tout + (size_t)b * HH * WW);
    const float*  sI = sIw[wib];

    // interior: all touched rows within [0, HH) and no y-boundary derivative rows
    if (band > 0 && band < BANDS - 1)
        run_band<true >(Tb, ub, vb, mb, Ob, sI, y0, c, emitl, zL, zR, sdy, s2dy);
    else
        run_band<false>(Tb, ub, vb, mb, Ob, sI, y0, c, emitl, zL, zR, sdy, s2dy);
}

extern "C" void kernel_launch(void* const* d_in, const int* in_sizes, int n_in,
                              void* d_out, int out_size)
{
    const float* T    = (const float*)d_in[0];
    const float* ug   = (const float*)d_in[1];
    const float* vg   = (const float*)d_in[2];
    const float* lat  = (const float*)d_in[3];
    const float* lon  = (const float*)d_in[4];
    const float* mask = (const float*)d_in[5];
    float* out = (float*)d_out;

    float *bufA = nullptr, *bufB = nullptr;
    cudaGetSymbolAddress((void**)&bufA, g_bufA);
    cudaGetSymbolAddress((void**)&bufB, g_bufB);

    const int nwarps = SEGS * BANDS * BB;   // 13*36*8 = 3744
    dim3 grid(nwarps / 4);                  // 936 blocks
    dim3 block(128);

    const float* cur = T;
    const int npairs = NSTEPS / 2;          // 10 fused launches
    for (int p = 0; p < npairs; ++p) {
        float* dst = (p == npairs - 1) ? out : ((p & 1) ? bufB : bufA);
        ocean_step2<<<grid, block>>>(cur, dst, ug, vg, lat, lon, mask);
        cur = dst;
    }
}

// round 8
// speedup vs baseline: 1.0932x; 1.0932x over previous
#include <cuda_runtime.h>

#define HH 360
#define WW 720
#define W2 360
#define BB 8
#define TYS 15
#define NITER (TYS + 6)       // 21
#define NTAB  (NITER + 2)     // 23 rows: y0-5 .. y0+TYS+2
#define SEGS 13               // 13*28 = 364 >= 360 float2 cols (wrap, dup writes identical)
#define BANDS (HH / TYS)      // 24
#define NSTEPS 20
#define FULLM 0xffffffffu

// Ping-pong scratch (allocation-free: __device__ globals).
__device__ float g_bufA[BB * HH * WW];
__device__ float g_bufB[BB * HH * WW];

__device__ __forceinline__ float2 f2z() { return make_float2(0.f, 0.f); }
__device__ __forceinline__ int rclamp(int r) { return min(max(r, 0), HH - 1); }

// Two fused timesteps, 6-stage rolling pipeline down y.
// DT(=600) is pre-folded into sI (x-derivative table) and sdyD/s2dyD, so
// A = T - (u*dtx + v*dty)*m with no separate DT multiply.
// Stages 2/3/4 are compile-time gated during pipeline fill (rings start at 0).
template <bool IN>
__device__ __forceinline__ void run_band(
    const float2* __restrict__ Tb, const float2* __restrict__ ub,
    const float2* __restrict__ vb, const float2* __restrict__ mb,
    float2* __restrict__ Ob, const float* __restrict__ sI,
    const int y0, const int c, const bool emitl, const bool zL, const bool zR,
    const float sdyD, const float s2dyD)
{
    float2 T0, T1, TPf, uPf, vPf, mPf;
    {
        const int r0 = IN ? (y0 - 4) : rclamp(y0 - 4);
        const int r1 = IN ? (y0 - 3) : rclamp(y0 - 3);
        const int r2 = IN ? (y0 - 2) : rclamp(y0 - 2);
        T0  = Tb[r0 * W2 + c];
        T1  = Tb[r1 * W2 + c];
        TPf = Tb[r2 * W2 + c];
        uPf = ub[r1 * W2 + c];
        vPf = vb[r1 * W2 + c];
        mPf = mb[r1 * W2 + c];
    }

    float2 h1a = f2z(), h1b = f2z(), h1c = f2z();
    float2 F1a = f2z(), F1b = f2z(), F1c = f2z();
    float2 h2a = f2z(), h2b = f2z(), h2c = f2z();
    float2 uC = f2z(), u1 = f2z(), u2 = f2z();
    float2 vC = f2z(), v1 = f2z(), v2 = f2z();
    float2 mC = f2z(), m1 = f2z(), m2 = f2z(), m3 = f2z();

#pragma unroll
    for (int k = 0; k < NITER; ++k) {
        const int a = y0 - 3 + k;       // step-1 advection row

        // ring shifts (renamed by full unroll; required even in gated iters)
        m3 = m2; m2 = m1; m1 = mC;
        u2 = u1; u1 = uC;
        v2 = v1; v1 = vC;
        const float2 T2 = TPf;
        uC = uPf; vC = vPf; mC = mPf;

        // prefetch next iteration's rows (T: a+2, u/v/m: a+1)
        {
            const int rT = IN ? (a + 2) : rclamp(a + 2);
            const int rU = IN ? (a + 1) : rclamp(a + 1);
            TPf = Tb[rT * W2 + c];
            uPf = ub[rU * W2 + c];
            vPf = vb[rU * W2 + c];
            mPf = mb[rU * W2 + c];
        }

        // ---- stage 1: advection step 1 + horizontal (1,2,1) at row a
        h1a = h1b; h1b = h1c;
        {
            const float iA = sI[k + 2];
            float dty0, dty1;
            if (IN) {
                dty0 = (T2.x - T0.x) * s2dyD;
                dty1 = (T2.y - T0.y) * s2dyD;
            } else {
                const float cA = (a == 0) ? sdyD  : ((a == HH - 1) ? 0.f   : s2dyD);
                const float cB = (a == 0) ? -sdyD : ((a == HH - 1) ? sdyD  : 0.f);
                const float cC = (a == 0) ? 0.f   : ((a == HH - 1) ? -sdyD : -s2dyD);
                dty0 = cA * T2.x + cB * T1.x + cC * T0.x;
                dty1 = cA * T2.y + cB * T1.y + cC * T0.y;
            }
            const float lf = __shfl_up_sync(FULLM, T1.y, 1);
            const float rt = __shfl_down_sync(FULLM, T1.x, 1);
            const float A0 = T1.x - (uC.x * ((T1.y - lf) * iA) + vC.x * dty0) * mC.x;
            const float A1 = T1.y - (uC.y * ((rt - T1.x) * iA) + vC.y * dty1) * mC.y;
            float Am = __shfl_up_sync(FULLM, A1, 1);
            float Ap = __shfl_down_sync(FULLM, A0, 1);
            Am = zL ? 0.f : Am;
            Ap = zR ? 0.f : Ap;
            float hx = Am + 2.f * A0 + A1;
            float hy = A0 + 2.f * A1 + Ap;
            if (!IN && !(a >= 0 && a < HH)) { hx = 0.f; hy = 0.f; }
            h1c.x = hx; h1c.y = hy;
        }

        // ---- stage 2: vertical (1,2,1)/16 * mask -> F1 at row f = a-1
        F1a = F1b; F1b = F1c;
        if (k >= 2) {
            float fx = (h1a.x + 2.f * h1b.x + h1c.x) * 0.0625f * m1.x;
            float fy = (h1a.y + 2.f * h1b.y + h1c.y) * 0.0625f * m1.y;
            if (!IN) { const int f = a - 1; if (!(f >= 0 && f < HH)) { fx = 0.f; fy = 0.f; } }
            F1c.x = fx; F1c.y = fy;
        }

        // ---- stage 3: advection step 2 + horizontal (1,2,1) at row g = a-2
        h2a = h2b; h2b = h2c;
        if (k >= 4) {
            const int g = a - 2;
            const float iG = sI[k];
            float dty0, dty1;
            if (IN) {
                dty0 = (F1c.x - F1a.x) * s2dyD;
                dty1 = (F1c.y - F1a.y) * s2dyD;
            } else {
                const float cA = (g == 0) ? sdyD  : ((g == HH - 1) ? 0.f   : s2dyD);
                const float cB = (g == 0) ? -sdyD : ((g == HH - 1) ? sdyD  : 0.f);
                const float cC = (g == 0) ? 0.f   : ((g == HH - 1) ? -sdyD : -s2dyD);
                dty0 = cA * F1c.x + cB * F1b.x + cC * F1a.x;
                dty1 = cA * F1c.y + cB * F1b.y + cC * F1a.y;
            }
            const float lf = __shfl_up_sync(FULLM, F1b.y, 1);
            const float rt = __shfl_down_sync(FULLM, F1b.x, 1);
            const float A0 = F1b.x - (u2.x * ((F1b.y - lf) * iG) + v2.x * dty0) * m2.x;
            const float A1 = F1b.y - (u2.y * ((rt - F1b.x) * iG) + v2.y * dty1) * m2.y;
            float Am = __shfl_up_sync(FULLM, A1, 1);
            float Ap = __shfl_down_sync(FULLM, A0, 1);
            Am = zL ? 0.f : Am;
            Ap = zR ? 0.f : Ap;
            float hx = Am + 2.f * A0 + A1;
            float hy = A0 + 2.f * A1 + Ap;
            if (!IN && !(g >= 0 && g < HH)) { hx = 0.f; hy = 0.f; }
            h2c.x = hx; h2c.y = hy;
        }

        // ---- stage 4: vertical (1,2,1)/16 * mask -> emit row e = a-3
        if (k >= 6) {
            if (emitl) {
                const int e = a - 3;        // in [y0, y0+TYS)
                float2 o;
                o.x = (h2a.x + 2.f * h2b.x + h2c.x) * 0.0625f * m3.x;
                o.y = (h2a.y + 2.f * h2b.y + h2c.y) * 0.0625f * m3.y;
                Ob[e * W2 + c] = o;
            }
        }

        T0 = T1; T1 = T2;
    }
}

__global__ __launch_bounds__(128, 6) void ocean_step2(
    const float* __restrict__ Tin, float* __restrict__ Tout,
    const float* __restrict__ ug, const float* __restrict__ vg,
    const float* __restrict__ lat, const float* __restrict__ lon,
    const float* __restrict__ mask)
{
    __shared__ float sIw[4][NTAB];    // per-warp DT/(2dx) tables

    const int tid  = threadIdx.x;
    const int lane = tid & 31;
    const int wib  = tid >> 5;
    const int ws   = blockIdx.x * 4 + wib;
    const int seg  = ws % SEGS;
    const int rem  = ws / SEGS;
    const int band = rem % BANDS;
    const int b    = rem / BANDS;
    const int y0   = band * TYS;

    // lane -> float2 column (wrapped). Lanes 2..29 emit.
    int c = seg * 28 - 2 + lane;
    c += (c < 0) ? W2 : 0;
    c -= (c >= W2) ? W2 : 0;
    const bool emitl = (lane >= 2) && (lane <= 29);
    const bool zL = (c == 0);
    const bool zR = (c == W2 - 1);

    const float DEG2RAD = 0.017453292519943295f;
    const float RE = 6371000.0f, DTC = 600.0f;
    const float dlat = lat[1] - lat[0];
    const float dlon = lon[1] - lon[0];
    const float dy   = RE * DEG2RAD * fabsf(dlat);
    const float sgn  = (dlat > 0.f) ? 1.f : -1.f;
    const float sdyD  = DTC * sgn / dy;           // DT folded in
    const float s2dyD = DTC * sgn / (2.f * dy);
    const float xden = 2.f * RE * DEG2RAD * dlon;

    // fill this warp's DT/(2dx) table: rows y0-5 .. y0+TYS+2 (clamped)
    if (lane < NTAB) {
        const int r = rclamp(y0 - 5 + lane);
        sIw[wib][lane] = __fdividef(DTC, xden * __cosf(lat[r] * DEG2RAD));
    }
    __syncwarp();

    const float2* Tb = (const float2*)(Tin + (size_t)b * HH * WW);
    const float2* ub = (const float2*)(ug  + (size_t)b * HH * WW);
    const float2* vb = (const float2*)(vg  + (size_t)b * HH * WW);
    const float2* mb = (const float2*)mask;
    float2*       Ob = (float2*)(Tout + (size_t)b * HH * WW);
    const float*  sI = sIw[wib];

    // interior: all touched rows within [0, HH) and no y-boundary derivative rows
    if (band > 0 && band < BANDS - 1)
        run_band<true >(Tb, ub, vb, mb, Ob, sI, y0, c, emitl, zL, zR, sdyD, s2dyD);
    else
        run_band<false>(Tb, ub, vb, mb, Ob, sI, y0, c, emitl, zL, zR, sdyD, s2dyD);
}

extern "C" void kernel_launch(void* const* d_in, const int* in_sizes, int n_in,
                              void* d_out, int out_size)
{
    const float* T    = (const float*)d_in[0];
    const float* ug   = (const float*)d_in[1];
    const float* vg   = (const float*)d_in[2];
    const float* lat  = (const float*)d_in[3];
    const float* lon  = (const float*)d_in[4];
    const float* mask = (const float*)d_in[5];
    float* out = (float*)d_out;

    float *bufA = nullptr, *bufB = nullptr;
    cudaGetSymbolAddress((void**)&bufA, g_bufA);
    cudaGetSymbolAddress((void**)&bufB, g_bufB);

    const int nwarps = SEGS * BANDS * BB;   // 13*24*8 = 2496
    dim3 grid(nwarps / 4);                  // 624 blocks
    dim3 block(128);

    const float* cur = T;
    const int npairs = NSTEPS / 2;          // 10 fused launches
    for (int p = 0; p < npairs; ++p) {
        float* dst = (p == npairs - 1) ? out : ((p & 1) ? bufB : bufA);
        ocean_step2<<<grid, block>>>(cur, dst, ug, vg, lat, lon, mask);
        cur = dst;
    }
}

// round 9
// speedup vs baseline: 1.2275x; 1.1228x over previous
#include <cuda_runtime.h>
#include <cuda_fp16.h>

#define HH 360
#define WW 720
#define W2 360
#define HW (HH * WW)
#define BB 8
#define TYS 15
#define NITER (TYS + 6)       // 21
#define NTAB  (NITER + 2)     // 23 rows: y0-5 .. y0+TYS+2
#define SEGS 13               // 13*28 = 364 >= 360 float2 cols (wrap, dup writes identical)
#define BANDS (HH / TYS)      // 24
#define NSTEPS 20
#define FULLM 0xffffffffu

// Scratch (allocation-free: __device__ globals).
__device__ float g_bufA[BB * HW];
__device__ float g_bufB[BB * HW];
__device__ unsigned int g_uvm[BB * HW];   // half2(u*m, v*m) per scalar point
__device__ __half g_ms[HW];               // half(m * 0.0625), 2D (batch-shared)

__device__ __forceinline__ float2 f2z() { return make_float2(0.f, 0.f); }
__device__ __forceinline__ int rclamp(int r) { return min(max(r, 0), HH - 1); }

// ---- prologue: pack u*m, v*m (fp16) and m*0.0625 (fp16), once per run
__global__ void pack_kernel(const float* __restrict__ u,
                            const float* __restrict__ v,
                            const float* __restrict__ m)
{
    const int stride = gridDim.x * blockDim.x;
    for (int j = blockIdx.x * blockDim.x + threadIdx.x; j < HW; j += stride) {
        const float mm = m[j];
        g_ms[j] = __float2half_rn(mm * 0.0625f);
#pragma unroll
        for (int b = 0; b < BB; ++b) {
            const int i = b * HW + j;
            const __half2 p = __floats2half2_rn(u[i] * mm, v[i] * mm);
            g_uvm[i] = *(const unsigned int*)&p;
        }
    }
}

// Two fused timesteps, 6-stage rolling pipeline down y.
// DT folded into sI / sdyD / s2dyD; mask folded into uvm (advection) and ms (filter).
template <bool IN>
__device__ __forceinline__ void run_band(
    const float2* __restrict__ Tb, const uint2* __restrict__ Ab,
    const __half2* __restrict__ Mb, float2* __restrict__ Ob,
    const float* __restrict__ sI,
    const int y0, const int c, const bool emitl, const bool zL, const bool zR,
    const float sdyD, const float s2dyD)
{
    float2 T0, T1, TPf;
    uint2  aPf;          // packed (um,vm) for 2 scalar cols
    __half2 mPf;         // packed ms for 2 scalar cols
    {
        const int r0 = IN ? (y0 - 4) : rclamp(y0 - 4);
        const int r1 = IN ? (y0 - 3) : rclamp(y0 - 3);
        const int r2 = IN ? (y0 - 2) : rclamp(y0 - 2);
        T0  = Tb[r0 * W2 + c];
        T1  = Tb[r1 * W2 + c];
        TPf = Tb[r2 * W2 + c];
        aPf = Ab[r1 * W2 + c];
        mPf = Mb[r1 * W2 + c];
    }

    float2 h1a = f2z(), h1b = f2z(), h1c = f2z();
    float2 F1a = f2z(), F1b = f2z(), F1c = f2z();
    float2 h2a = f2z(), h2b = f2z(), h2c = f2z();
    float2 uC = f2z(), u1 = f2z(), u2 = f2z();     // um rings
    float2 vC = f2z(), v1 = f2z(), v2 = f2z();     // vm rings
    float2 mC = f2z(), m1 = f2z(), m2 = f2z(), m3 = f2z();  // ms rings

#pragma unroll
    for (int k = 0; k < NITER; ++k) {
        const int a = y0 - 3 + k;       // step-1 advection row

        // ring shifts (renamed by full unroll)
        m3 = m2; m2 = m1; m1 = mC;
        u2 = u1; u1 = uC;
        v2 = v1; v1 = vC;
        const float2 T2 = TPf;
        // unpack prefetched operands
        {
            const __half2 p0 = *(const __half2*)&aPf.x;   // (um0, vm0)
            const __half2 p1 = *(const __half2*)&aPf.y;   // (um1, vm1)
            const float2 f0 = __half22float2(p0);
            const float2 f1 = __half22float2(p1);
            uC = make_float2(f0.x, f1.x);
            vC = make_float2(f0.y, f1.y);
            mC = __half22float2(mPf);
        }

        // prefetch next iteration's rows (T: a+2, uvm/ms: a+1)
        {
            const int rT = IN ? (a + 2) : rclamp(a + 2);
            const int rU = IN ? (a + 1) : rclamp(a + 1);
            TPf = Tb[rT * W2 + c];
            aPf = Ab[rU * W2 + c];
            mPf = Mb[rU * W2 + c];
        }

        // ---- stage 1: advection step 1 + horizontal (1,2,1) at row a
        h1a = h1b; h1b = h1c;
        {
            const float iA = sI[k + 2];
            float dty0, dty1;
            if (IN) {
                dty0 = (T2.x - T0.x) * s2dyD;
                dty1 = (T2.y - T0.y) * s2dyD;
            } else {
                const float cA = (a == 0) ? sdyD  : ((a == HH - 1) ? 0.f   : s2dyD);
                const float cB = (a == 0) ? -sdyD : ((a == HH - 1) ? sdyD  : 0.f);
                const float cC = (a == 0) ? 0.f   : ((a == HH - 1) ? -sdyD : -s2dyD);
                dty0 = cA * T2.x + cB * T1.x + cC * T0.x;
                dty1 = cA * T2.y + cB * T1.y + cC * T0.y;
            }
            const float lf = __shfl_up_sync(FULLM, T1.y, 1);
            const float rt = __shfl_down_sync(FULLM, T1.x, 1);
            const float A0 = T1.x - (uC.x * ((T1.y - lf) * iA) + vC.x * dty0);
            const float A1 = T1.y - (uC.y * ((rt - T1.x) * iA) + vC.y * dty1);
            float Am = __shfl_up_sync(FULLM, A1, 1);
            float Ap = __shfl_down_sync(FULLM, A0, 1);
            Am = zL ? 0.f : Am;
            Ap = zR ? 0.f : Ap;
            float hx = Am + 2.f * A0 + A1;
            float hy = A0 + 2.f * A1 + Ap;
            if (!IN && !(a >= 0 && a < HH)) { hx = 0.f; hy = 0.f; }
            h1c.x = hx; h1c.y = hy;
        }

        // ---- stage 2: vertical (1,2,1)*ms -> F1 at row f = a-1
        F1a = F1b; F1b = F1c;
        if (k >= 2) {
            float fx = (h1a.x + 2.f * h1b.x + h1c.x) * m1.x;
            float fy = (h1a.y + 2.f * h1b.y + h1c.y) * m1.y;
            if (!IN) { const int f = a - 1; if (!(f >= 0 && f < HH)) { fx = 0.f; fy = 0.f; } }
            F1c.x = fx; F1c.y = fy;
        }

        // ---- stage 3: advection step 2 + horizontal (1,2,1) at row g = a-2
        h2a = h2b; h2b = h2c;
        if (k >= 4) {
            const int g = a - 2;
            const float iG = sI[k];
            float dty0, dty1;
            if (IN) {
                dty0 = (F1c.x - F1a.x) * s2dyD;
                dty1 = (F1c.y - F1a.y) * s2dyD;
            } else {
                const float cA = (g == 0) ? sdyD  : ((g == HH - 1) ? 0.f   : s2dyD);
                const float cB = (g == 0) ? -sdyD : ((g == HH - 1) ? sdyD  : 0.f);
                const float cC = (g == 0) ? 0.f   : ((g == HH - 1) ? -sdyD : -s2dyD);
                dty0 = cA * F1c.x + cB * F1b.x + cC * F1a.x;
                dty1 = cA * F1c.y + cB * F1b.y + cC * F1a.y;
            }
            const float lf = __shfl_up_sync(FULLM, F1b.y, 1);
            const float rt = __shfl_down_sync(FULLM, F1b.x, 1);
            const float A0 = F1b.x - (u2.x * ((F1b.y - lf) * iG) + v2.x * dty0);
            const float A1 = F1b.y - (u2.y * ((rt - F1b.x) * iG) + v2.y * dty1);
            float Am = __shfl_up_sync(FULLM, A1, 1);
            float Ap = __shfl_down_sync(FULLM, A0, 1);
            Am = zL ? 0.f : Am;
            Ap = zR ? 0.f : Ap;
            float hx = Am + 2.f * A0 + A1;
            float hy = A0 + 2.f * A1 + Ap;
            if (!IN && !(g >= 0 && g < HH)) { hx = 0.f; hy = 0.f; }
            h2c.x = hx; h2c.y = hy;
        }

        // ---- stage 4: vertical (1,2,1)*ms -> emit row e = a-3
        if (k >= 6) {
            if (emitl) {
                const int e = a - 3;        // in [y0, y0+TYS)
                float2 o;
                o.x = (h2a.x + 2.f * h2b.x + h2c.x) * m3.x;
                o.y = (h2a.y + 2.f * h2b.y + h2c.y) * m3.y;
                Ob[e * W2 + c] = o;
            }
        }

        T0 = T1; T1 = T2;
    }
}

__global__ __launch_bounds__(128, 6) void ocean_step2(
    const float* __restrict__ Tin, float* __restrict__ Tout,
    const float* __restrict__ lat, const float* __restrict__ lon)
{
    __shared__ float sIw[4][NTAB];    // per-warp DT/(2dx) tables

    const int tid  = threadIdx.x;
    const int lane = tid & 31;
    const int wib  = tid >> 5;
    const int ws   = blockIdx.x * 4 + wib;
    const int seg  = ws % SEGS;
    const int rem  = ws / SEGS;
    const int band = rem % BANDS;
    const int b    = rem / BANDS;
    const int y0   = band * TYS;

    // lane -> float2 column (wrapped). Lanes 2..29 emit.
    int c = seg * 28 - 2 + lane;
    c += (c < 0) ? W2 : 0;
    c -= (c >= W2) ? W2 : 0;
    const bool emitl = (lane >= 2) && (lane <= 29);
    const bool zL = (c == 0);
    const bool zR = (c == W2 - 1);

    const float DEG2RAD = 0.017453292519943295f;
    const float RE = 6371000.0f, DTC = 600.0f;
    const float dlat = lat[1] - lat[0];
    const float dlon = lon[1] - lon[0];
    const float dy   = RE * DEG2RAD * fabsf(dlat);
    const float sgn  = (dlat > 0.f) ? 1.f : -1.f;
    const float sdyD  = DTC * sgn / dy;           // DT folded in
    const float s2dyD = DTC * sgn / (2.f * dy);
    const float xden = 2.f * RE * DEG2RAD * dlon;

    // fill this warp's DT/(2dx) table: rows y0-5 .. y0+TYS+2 (clamped)
    if (lane < NTAB) {
        const int r = rclamp(y0 - 5 + lane);
        sIw[wib][lane] = __fdividef(DTC, xden * __cosf(lat[r] * DEG2RAD));
    }
    __syncwarp();

    const float2*  Tb = (const float2*)(Tin + (size_t)b * HW);
    const uint2*   Ab = (const uint2*)(g_uvm + (size_t)b * HW);
    const __half2* Mb = (const __half2*)g_ms;
    float2*        Ob = (float2*)(Tout + (size_t)b * HW);
    const float*   sI = sIw[wib];

    if (band > 0 && band < BANDS - 1)
        run_band<true >(Tb, Ab, Mb, Ob, sI, y0, c, emitl, zL, zR, sdyD, s2dyD);
    else
        run_band<false>(Tb, Ab, Mb, Ob, sI, y0, c, emitl, zL, zR, sdyD, s2dyD);
}

extern "C" void kernel_launch(void* const* d_in, const int* in_sizes, int n_in,
                              void* d_out, int out_size)
{
    const float* T    = (const float*)d_in[0];
    const float* ug   = (const float*)d_in[1];
    const float* vg   = (const float*)d_in[2];
    const float* lat  = (const float*)d_in[3];
    const float* lon  = (const float*)d_in[4];
    const float* mask = (const float*)d_in[5];
    float* out = (float*)d_out;

    float *bufA = nullptr, *bufB = nullptr;
    cudaGetSymbolAddress((void**)&bufA, g_bufA);
    cudaGetSymbolAddress((void**)&bufB, g_bufB);

    pack_kernel<<<296, 256>>>(ug, vg, mask);

    const int nwarps = SEGS * BANDS * BB;   // 13*24*8 = 2496
    dim3 grid(nwarps / 4);                  // 624 blocks
    dim3 block(128);

    const float* cur = T;
    const int npairs = NSTEPS / 2;          // 10 fused launches
    for (int p = 0; p < npairs; ++p) {
        float* dst = (p == npairs - 1) ? out : ((p & 1) ? bufB : bufA);
        ocean_step2<<<grid, block>>>(cur, dst, lat, lon);
        cur = dst;
    }
}

// round 10
// speedup vs baseline: 1.3726x; 1.1183x over previous
#include <cuda_runtime.h>
#include <cuda_fp16.h>

#define HH 360
#define WW 720
#define W2 360
#define HW (HH * WW)
#define BB 8
#define TYS 15
#define NITER (TYS + 6)       // 21
#define NTAB  (NITER + 2)     // 23 rows: y0-5 .. y0+TYS+2
#define SEGS 13               // 13*28 = 364 >= 360 float2 cols (wrap, dup writes identical)
#define BANDS (HH / TYS)      // 24
#define NSTEPS 20
#define FULLM 0xffffffffu

// Scratch (allocation-free: __device__ globals).
__device__ float g_bufA[BB * HW];
__device__ float g_bufB[BB * HW];
__device__ unsigned int g_uvm[BB * HW];   // half2(u*m, v*m) per scalar point
__device__ __half g_ms[HW];               // half(m * 0.0625), 2D (batch-shared)

__device__ __forceinline__ float2 f2z() { return make_float2(0.f, 0.f); }
__device__ __forceinline__ int rclamp(int r) { return min(max(r, 0), HH - 1); }

// ---- prologue: pack u*m, v*m (fp16) and m*0.0625 (fp16), once per run
__global__ void pack_kernel(const float* __restrict__ u,
                            const float* __restrict__ v,
                            const float* __restrict__ m)
{
    const int stride = gridDim.x * blockDim.x;
    for (int j = blockIdx.x * blockDim.x + threadIdx.x; j < HW; j += stride) {
        const float mm = m[j];
        g_ms[j] = __float2half_rn(mm * 0.0625f);
#pragma unroll
        for (int b = 0; b < BB; ++b) {
            const int i = b * HW + j;
            const __half2 p = __floats2half2_rn(u[i] * mm, v[i] * mm);
            g_uvm[i] = *(const unsigned int*)&p;
        }
    }
}

// Two fused timesteps, 6-stage rolling pipeline down y.
// 2-deep prefetch; per-row DT/(2dx) table lives in lane registers (shfl access).
template <bool IN>
__device__ __forceinline__ void run_band(
    const float2* __restrict__ Tb, const uint2* __restrict__ Ab,
    const __half2* __restrict__ Mb, float2* __restrict__ Ob,
    const float tabI,
    const int y0, const int c, const bool emitl, const bool zL, const bool zR,
    const float sdyD, const float s2dyD)
{
    float2 T0, T1, TPf1, TPf2;
    uint2  aPf1, aPf2;
    __half2 mPf1, mPf2;
    {
        const int r0 = IN ? (y0 - 4) : rclamp(y0 - 4);
        const int r1 = IN ? (y0 - 3) : rclamp(y0 - 3);
        const int r2 = IN ? (y0 - 2) : rclamp(y0 - 2);
        const int r3 = IN ? (y0 - 1) : rclamp(y0 - 1);
        T0   = Tb[r0 * W2 + c];
        T1   = Tb[r1 * W2 + c];
        TPf1 = Tb[r2 * W2 + c];
        TPf2 = Tb[r3 * W2 + c];
        aPf1 = Ab[r1 * W2 + c];
        aPf2 = Ab[r2 * W2 + c];
        mPf1 = Mb[r1 * W2 + c];
        mPf2 = Mb[r2 * W2 + c];
    }

    float2 h1a = f2z(), h1b = f2z(), h1c = f2z();
    float2 F1a = f2z(), F1b = f2z(), F1c = f2z();
    float2 h2a = f2z(), h2b = f2z(), h2c = f2z();
    float2 uC = f2z(), u1 = f2z(), u2 = f2z();
    float2 vC = f2z(), v1 = f2z(), v2 = f2z();
    float2 mC = f2z(), m1 = f2z(), m2 = f2z(), m3 = f2z();

#pragma unroll
    for (int k = 0; k < NITER; ++k) {
        const int a = y0 - 3 + k;       // step-1 advection row

        // ring shifts (renamed by full unroll)
        m3 = m2; m2 = m1; m1 = mC;
        u2 = u1; u1 = uC;
        v2 = v1; v1 = vC;
        const float2 T2 = TPf1;  TPf1 = TPf2;
        // unpack prefetched uvm/ms for row a
        {
            const __half2 p0 = *(const __half2*)&aPf1.x;   // (um0, vm0)
            const __half2 p1 = *(const __half2*)&aPf1.y;   // (um1, vm1)
            const float2 f0 = __half22float2(p0);
            const float2 f1 = __half22float2(p1);
            uC = make_float2(f0.x, f1.x);
            vC = make_float2(f0.y, f1.y);
            mC = __half22float2(mPf1);
        }
        aPf1 = aPf2;  mPf1 = mPf2;

        // 2-deep prefetch (T: a+3, uvm/ms: a+2)
        {
            const int rT = IN ? (a + 3) : rclamp(a + 3);
            const int rU = IN ? (a + 2) : rclamp(a + 2);
            TPf2 = Tb[rT * W2 + c];
            aPf2 = Ab[rU * W2 + c];
            mPf2 = Mb[rU * W2 + c];
        }

        // ---- stage 1: advection step 1 + horizontal (1,2,1) at row a
        h1a = h1b; h1b = h1c;
        {
            const float iA = __shfl_sync(FULLM, tabI, k + 2);
            float dty0, dty1;
            if (IN) {
                dty0 = (T2.x - T0.x) * s2dyD;
                dty1 = (T2.y - T0.y) * s2dyD;
            } else {
                const float cA = (a == 0) ? sdyD  : ((a == HH - 1) ? 0.f   : s2dyD);
                const float cB = (a == 0) ? -sdyD : ((a == HH - 1) ? sdyD  : 0.f);
                const float cC = (a == 0) ? 0.f   : ((a == HH - 1) ? -sdyD : -s2dyD);
                dty0 = cA * T2.x + cB * T1.x + cC * T0.x;
                dty1 = cA * T2.y + cB * T1.y + cC * T0.y;
            }
            const float lf = __shfl_up_sync(FULLM, T1.y, 1);
            const float rt = __shfl_down_sync(FULLM, T1.x, 1);
            const float A0 = T1.x - (uC.x * ((T1.y - lf) * iA) + vC.x * dty0);
            const float A1 = T1.y - (uC.y * ((rt - T1.x) * iA) + vC.y * dty1);
            float Am = __shfl_up_sync(FULLM, A1, 1);
            float Ap = __shfl_down_sync(FULLM, A0, 1);
            Am = zL ? 0.f : Am;
            Ap = zR ? 0.f : Ap;
            float hx = Am + 2.f * A0 + A1;
            float hy = A0 + 2.f * A1 + Ap;
            if (!IN && !(a >= 0 && a < HH)) { hx = 0.f; hy = 0.f; }
            h1c.x = hx; h1c.y = hy;
        }

        // ---- stage 2: vertical (1,2,1)*ms -> F1 at row f = a-1
        F1a = F1b; F1b = F1c;
        if (k >= 2) {
            float fx = (h1a.x + 2.f * h1b.x + h1c.x) * m1.x;
            float fy = (h1a.y + 2.f * h1b.y + h1c.y) * m1.y;
            if (!IN) { const int f = a - 1; if (!(f >= 0 && f < HH)) { fx = 0.f; fy = 0.f; } }
            F1c.x = fx; F1c.y = fy;
        }

        // ---- stage 3: advection step 2 + horizontal (1,2,1) at row g = a-2
        h2a = h2b; h2b = h2c;
        if (k >= 4) {
            const int g = a - 2;
            const float iG = __shfl_sync(FULLM, tabI, k);
            float dty0, dty1;
            if (IN) {
                dty0 = (F1c.x - F1a.x) * s2dyD;
                dty1 = (F1c.y - F1a.y) * s2dyD;
            } else {
                const float cA = (g == 0) ? sdyD  : ((g == HH - 1) ? 0.f   : s2dyD);
                const float cB = (g == 0) ? -sdyD : ((g == HH - 1) ? sdyD  : 0.f);
                const float cC = (g == 0) ? 0.f   : ((g == HH - 1) ? -sdyD : -s2dyD);
                dty0 = cA * F1c.x + cB * F1b.x + cC * F1a.x;
                dty1 = cA * F1c.y + cB * F1b.y + cC * F1a.y;
            }
            const float lf = __shfl_up_sync(FULLM, F1b.y, 1);
            const float rt = __shfl_down_sync(FULLM, F1b.x, 1);
            const float A0 = F1b.x - (u2.x * ((F1b.y - lf) * iG) + v2.x * dty0);
            const float A1 = F1b.y - (u2.y * ((rt - F1b.x) * iG) + v2.y * dty1);
            float Am = __shfl_up_sync(FULLM, A1, 1);
            float Ap = __shfl_down_sync(FULLM, A0, 1);
            Am = zL ? 0.f : Am;
            Ap = zR ? 0.f : Ap;
            float hx = Am + 2.f * A0 + A1;
            float hy = A0 + 2.f * A1 + Ap;
            if (!IN && !(g >= 0 && g < HH)) { hx = 0.f; hy = 0.f; }
            h2c.x = hx; h2c.y = hy;
        }

        // ---- stage 4: vertical (1,2,1)*ms -> emit row e = a-3
        if (k >= 6) {
            if (emitl) {
                const int e = a - 3;        // in [y0, y0+TYS)
                float2 o;
                o.x = (h2a.x + 2.f * h2b.x + h2c.x) * m3.x;
                o.y = (h2a.y + 2.f * h2b.y + h2c.y) * m3.y;
                Ob[e * W2 + c] = o;
            }
        }

        T0 = T1; T1 = T2;
    }
}

// One warp per block: fine-grained scheduling for SM load balance.
__global__ __launch_bounds__(32) void ocean_step2(
    const float* __restrict__ Tin, float* __restrict__ Tout,
    const float* __restrict__ lat, const float* __restrict__ lon)
{
    const int lane = threadIdx.x;
    const int ws   = blockIdx.x;
    const int seg  = ws % SEGS;
    const int rem  = ws / SEGS;
    const int band = rem % BANDS;
    const int b    = rem / BANDS;
    const int y0   = band * TYS;

    // lane -> float2 column (wrapped). Lanes 2..29 emit.
    int c = seg * 28 - 2 + lane;
    c += (c < 0) ? W2 : 0;
    c -= (c >= W2) ? W2 : 0;
    const bool emitl = (lane >= 2) && (lane <= 29);
    const bool zL = (c == 0);
    const bool zR = (c == W2 - 1);

    const float DEG2RAD = 0.017453292519943295f;
    const float RE = 6371000.0f, DTC = 600.0f;
    const float dlat = lat[1] - lat[0];
    const float dlon = lon[1] - lon[0];
    const float dy   = RE * DEG2RAD * fabsf(dlat);
    const float sgn  = (dlat > 0.f) ? 1.f : -1.f;
    const float sdyD  = DTC * sgn / dy;           // DT folded in
    const float s2dyD = DTC * sgn / (2.f * dy);
    const float xden = 2.f * RE * DEG2RAD * dlon;

    // per-lane DT/(2dx) table: lane k holds row y0-5+k (clamped); read via shfl
    const int tr = rclamp(y0 - 5 + min(lane, NTAB - 1));
    const float tabI = __fdividef(DTC, xden * __cosf(lat[tr] * DEG2RAD));

    const float2*  Tb = (const float2*)(Tin + (size_t)b * HW);
    const uint2*   Ab = (const uint2*)(g_uvm + (size_t)b * HW);
    const __half2* Mb = (const __half2*)g_ms;
    float2*        Ob = (float2*)(Tout + (size_t)b * HW);

    if (band > 0 && band < BANDS - 1)
        run_band<true >(Tb, Ab, Mb, Ob, tabI, y0, c, emitl, zL, zR, sdyD, s2dyD);
    else
        run_band<false>(Tb, Ab, Mb, Ob, tabI, y0, c, emitl, zL, zR, sdyD, s2dyD);
}

extern "C" void kernel_launch(void* const* d_in, const int* in_sizes, int n_in,
                              void* d_out, int out_size)
{
    const float* T    = (const float*)d_in[0];
    const float* ug   = (const float*)d_in[1];
    const float* vg   = (const float*)d_in[2];
    const float* lat  = (const float*)d_in[3];
    const float* lon  = (const float*)d_in[4];
    const float* mask = (const float*)d_in[5];
    float* out = (float*)d_out;

    float *bufA = nullptr, *bufB = nullptr;
    cudaGetSymbolAddress((void**)&bufA, g_bufA);
    cudaGetSymbolAddress((void**)&bufB, g_bufB);

    pack_kernel<<<296, 256>>>(ug, vg, mask);

    const int nblocks = SEGS * BANDS * BB;   // 13*24*8 = 2496 one-warp blocks
    dim3 grid(nblocks);
    dim3 block(32);

    const float* cur = T;
    const int npairs = NSTEPS / 2;           // 10 fused launches
    for (int p = 0; p < npairs; ++p) {
        float* dst = (p == npairs - 1) ? out : ((p & 1) ? bufB : bufA);
        ocean_step2<<<grid, block>>>(cur, dst, lat, lon);
        cur = dst;
    }
}